// round 10
// baseline (speedup 1.0000x reference)
#include <cuda_runtime.h>
#include <cuda_bf16.h>
#include <math.h>
#include <stdint.h>

#define BATCH 2
#define SEQ   2048
#define DM    1024
#define NH    16
#define HD    64
#define UTOP  38
#define QB    8
#define NELM  (BATCH*SEQ*DM)   // 4194304

// ---------------------------------------------------------------------------
// Scratch (allocation-free rule: __device__ globals)
// ---------------------------------------------------------------------------
__device__ float g_S[(size_t)BATCH*NH*SEQ*SEQ];   // 536 MB score matrix
__device__ float g_V[BATCH*NH*SEQ*HD];            // V, head-major fp32
__device__ __nv_bfloat16 g_xh[NELM],  g_xl[NELM];
__device__ __nv_bfloat16 g_Wvh[DM*DM], g_Wvl[DM*DM];
__device__ __nv_bfloat16 g_Woh[DM*DM], g_Wol[DM*DM];
__device__ __nv_bfloat16 g_Qh[NELM], g_Qm[NELM], g_Ql[NELM];   // head-major
__device__ __nv_bfloat16 g_Kh[NELM], g_Km[NELM], g_Kl[NELM];   // head-major
__device__ __nv_bfloat16 g_Ch[NELM], g_Cl[NELM];               // context hi/lo

// ---------------------------------------------------------------------------
// helpers
// ---------------------------------------------------------------------------
__device__ __forceinline__ unsigned f2u(float f) {
    unsigned u = __float_as_uint(f);
    return (u & 0x80000000u) ? ~u : (u | 0x80000000u);
}
__device__ __forceinline__ float u2f(unsigned m) {
    return __uint_as_float((m & 0x80000000u) ? (m & 0x7FFFFFFFu) : ~m);
}
__device__ __forceinline__ size_t hm_dest(int m, int n) {
    int b = m >> 11, q = m & (SEQ-1);
    int h = n >> 6,  d = n & (HD-1);
    return ((size_t)b << 21) + ((size_t)h << 17) + ((size_t)q << 6) + d;
}

// m16n8k16 bf16 MMA, fp32 accumulate (arch-neutral PTX -> HMMA on sm_103)
__device__ __forceinline__ void mma16816(float c[4], const uint32_t a[4],
                                         const uint32_t b[2]) {
    asm volatile(
        "mma.sync.aligned.m16n8k16.row.col.f32.bf16.bf16.f32 "
        "{%0,%1,%2,%3}, {%4,%5,%6,%7}, {%8,%9}, {%0,%1,%2,%3};"
        : "+f"(c[0]), "+f"(c[1]), "+f"(c[2]), "+f"(c[3])
        : "r"(a[0]), "r"(a[1]), "r"(a[2]), "r"(a[3]), "r"(b[0]), "r"(b[1]));
}

// ---------------------------------------------------------------------------
// bf16 split kernel: v -> hi + lo (residual ~2^-16 |v|)
// ---------------------------------------------------------------------------
__global__ void split2_kernel(const float* __restrict__ in,
                              __nv_bfloat16* __restrict__ hi,
                              __nv_bfloat16* __restrict__ lo, int n)
{
    int i = blockIdx.x * blockDim.x + threadIdx.x;
    if (i < n) {
        float v = in[i];
        __nv_bfloat16 h = __float2bfloat16(v);
        hi[i] = h;
        lo[i] = __float2bfloat16(v - __bfloat162float(h));
    }
}

// ---------------------------------------------------------------------------
// Tensor-core GEMM via mma.sync: C[M,N] = alpha*sum_pairs(Ai@Bj^T) + bias
// A planes [Mtot,K] bf16 row-major; B planes [Ntot,K] bf16 row-major
// (= col-major for mma.row.col). Block tile 128x64, 8 warps (4m x 2n),
// warp tile 32x32 = 2x4 m16n8k16, K chunks of 64 bf16, smem pitch 33 u32.
// NSPLIT=2: pairs hh,hl,lh ; NSPLIT=3: hh,hm,mh,mm,hl,lh
// ---------------------------------------------------------------------------
#define APU 4224   // A plane u32 (128*33)
#define BPU 2112   // B plane u32 (64*33)

template<int NSPLIT>
__global__ __launch_bounds__(256) void gemm_mma(
    const __nv_bfloat16* __restrict__ A0, const __nv_bfloat16* __restrict__ A1,
    const __nv_bfloat16* __restrict__ A2, int lda, size_t sA,
    const __nv_bfloat16* __restrict__ B0, const __nv_bfloat16* __restrict__ B1,
    const __nv_bfloat16* __restrict__ B2, int ldb, size_t sB,
    const float* __restrict__ bias,
    float* __restrict__ Cout, int ldc, size_t sC,
    int Kdim, float alpha, int headmajor)
{
    extern __shared__ uint32_t sm[];
    uint32_t* Asm = sm;                    // [NSPLIT][APU]
    uint32_t* Bsm = sm + NSPLIT*APU;       // [NSPLIT][BPU]

    const int t    = threadIdx.x;
    const int wid  = t >> 5, lane = t & 31;
    const int wm   = wid & 3, wn = wid >> 2;
    const int g    = lane >> 2;       // 0..7
    const int tq   = lane & 3;        // 0..3
    const int m0   = blockIdx.y * 128;
    const int n0   = blockIdx.x * 64;

    const uint32_t* Ap[3] = { (const uint32_t*)(A0 + blockIdx.z*sA),
                              (const uint32_t*)(A1 ? A1 + blockIdx.z*sA : A0),
                              (const uint32_t*)(A2 ? A2 + blockIdx.z*sA : A0) };
    const uint32_t* Bp[3] = { (const uint32_t*)(B0 + blockIdx.z*sB),
                              (const uint32_t*)(B1 ? B1 + blockIdx.z*sB : B0),
                              (const uint32_t*)(B2 ? B2 + blockIdx.z*sB : B0) };
    Cout += blockIdx.z * sC;

    float c[2][4][4];
    #pragma unroll
    for (int i = 0; i < 2; i++)
        #pragma unroll
        for (int j = 0; j < 4; j++)
            #pragma unroll
            for (int k = 0; k < 4; k++) c[i][j][k] = 0.f;

    const int lda2 = lda >> 1, ldb2 = ldb >> 1;
    const int nchunk = Kdim >> 6;

    const int npairs = (NSPLIT == 2) ? 3 : 6;
    const int pa[6] = {0,0,1,1,0,2};
    const int pb[6] = {0,1,0,1,2,0};

    for (int cc = 0; cc < nchunk; cc++) {
        if (cc) __syncthreads();
        int kb = cc << 5;   // u32 col base in global rows
        #pragma unroll
        for (int p = 0; p < NSPLIT; p++) {
            const uint32_t* src = Ap[p];
            #pragma unroll
            for (int i = 0; i < 16; i++) {
                int idx = t + (i << 8);                 // 0..4095
                int r = idx >> 5, col = idx & 31;
                Asm[p*APU + r*33 + col] = src[(size_t)(m0 + r)*lda2 + kb + col];
            }
            const uint32_t* srcB = Bp[p];
            #pragma unroll
            for (int i = 0; i < 8; i++) {
                int idx = t + (i << 8);                 // 0..2047
                int r = idx >> 5, col = idx & 31;
                Bsm[p*BPU + r*33 + col] = srcB[(size_t)(n0 + r)*ldb2 + kb + col];
            }
        }
        __syncthreads();

        #pragma unroll
        for (int ks = 0; ks < 4; ks++) {
            int kc = ks << 3;   // u32 col base of this k16 step
            #pragma unroll
            for (int pp = 0; pp < npairs; pp++) {
                const uint32_t* Aw = Asm + pa[pp]*APU;
                const uint32_t* Bw = Bsm + pb[pp]*BPU;
                uint32_t af[2][4];
                #pragma unroll
                for (int mt = 0; mt < 2; mt++) {
                    int row = wm*32 + mt*16 + g;
                    af[mt][0] = Aw[ row     *33 + kc + tq    ];
                    af[mt][1] = Aw[(row + 8)*33 + kc + tq    ];
                    af[mt][2] = Aw[ row     *33 + kc + 4 + tq];
                    af[mt][3] = Aw[(row + 8)*33 + kc + 4 + tq];
                }
                uint32_t bf[4][2];
                #pragma unroll
                for (int nt = 0; nt < 4; nt++) {
                    int n = wn*32 + nt*8 + g;
                    bf[nt][0] = Bw[n*33 + kc + tq    ];
                    bf[nt][1] = Bw[n*33 + kc + 4 + tq];
                }
                #pragma unroll
                for (int mt = 0; mt < 2; mt++)
                    #pragma unroll
                    for (int nt = 0; nt < 4; nt++)
                        mma16816(c[mt][nt], af[mt], bf[nt]);
            }
        }
    }

    // epilogue
    #pragma unroll
    for (int mt = 0; mt < 2; mt++) {
        #pragma unroll
        for (int half = 0; half < 2; half++) {
            int m = m0 + wm*32 + mt*16 + g + half*8;
            #pragma unroll
            for (int nt = 0; nt < 4; nt++) {
                int nloc = wn*32 + nt*8 + tq*2;
                int n = n0 + nloc;
                float2 r;
                float v0 = c[mt][nt][half*2+0];
                float v1 = c[mt][nt][half*2+1];
                r.x = alpha*v0 + (bias ? bias[n]   : 0.f);
                r.y = alpha*v1 + (bias ? bias[n+1] : 0.f);
                float* dst;
                if (headmajor) dst = Cout + hm_dest(m, n);
                else           dst = Cout + (size_t)m*ldc + n;
                *(float2*)dst = r;
            }
        }
    }
}

// ---------------------------------------------------------------------------
// High-accuracy two-level (Kahan) GEMM — Q/K projections; emits 3 bf16 planes
// head-major. (Same numerics as the passing round-6/7/8 kernels.)
// ---------------------------------------------------------------------------
__global__ __launch_bounds__(256) void gemm_2lvl(
    const float* __restrict__ A, int lda,
    const float* __restrict__ W, int ldw,
    const float* __restrict__ bias,
    __nv_bfloat16* __restrict__ Phi, __nv_bfloat16* __restrict__ Pmid,
    __nv_bfloat16* __restrict__ Plo, int Kdim)
{
    __shared__ float As[2][16][128];
    __shared__ float Ws[2][16][64];
    int t  = threadIdx.x;
    int m0 = blockIdx.y * 128;
    int n0 = blockIdx.x * 64;
    int tm = t >> 4, tn = t & 15;
    int lr = t >> 2;
    int lc = (t & 3) << 2;

    float acc[8][4], cmp[8][4];
    #pragma unroll
    for (int i = 0; i < 8; i++)
        #pragma unroll
        for (int j = 0; j < 4; j++) { acc[i][j] = 0.f; cmp[i][j] = 0.f; }

    float4 a0, a1, w0;
    a0 = *(const float4*)(A + (size_t)(m0+lr   )*lda + lc);
    a1 = *(const float4*)(A + (size_t)(m0+lr+64)*lda + lc);
    w0 = *(const float4*)(W + (size_t)(n0+lr   )*ldw + lc);
    As[0][lc+0][lr]    = a0.x; As[0][lc+1][lr]    = a0.y; As[0][lc+2][lr]    = a0.z; As[0][lc+3][lr]    = a0.w;
    As[0][lc+0][lr+64] = a1.x; As[0][lc+1][lr+64] = a1.y; As[0][lc+2][lr+64] = a1.z; As[0][lc+3][lr+64] = a1.w;
    Ws[0][lc+0][lr]    = w0.x; Ws[0][lc+1][lr]    = w0.y; Ws[0][lc+2][lr]    = w0.z; Ws[0][lc+3][lr]    = w0.w;
    __syncthreads();

    int nt = Kdim >> 4;
    for (int it = 0; it < nt; it++) {
        int cur = it & 1;
        if (it + 1 < nt) {
            int k0 = (it + 1) << 4;
            a0 = *(const float4*)(A + (size_t)(m0+lr   )*lda + k0 + lc);
            a1 = *(const float4*)(A + (size_t)(m0+lr+64)*lda + k0 + lc);
            w0 = *(const float4*)(W + (size_t)(n0+lr   )*ldw + k0 + lc);
        }
        float tmp[8][4];
        #pragma unroll
        for (int i = 0; i < 8; i++)
            #pragma unroll
            for (int j = 0; j < 4; j++) tmp[i][j] = 0.f;
        #pragma unroll
        for (int kk = 0; kk < 16; kk++) {
            float a[8], bb[4];
            *(float4*)(a)    = *(const float4*)&As[cur][kk][tm*8];
            *(float4*)(a+4)  = *(const float4*)&As[cur][kk][tm*8+4];
            *(float4*)(bb)   = *(const float4*)&Ws[cur][kk][tn*4];
            #pragma unroll
            for (int i = 0; i < 8; i++)
                #pragma unroll
                for (int j = 0; j < 4; j++)
                    tmp[i][j] = fmaf(a[i], bb[j], tmp[i][j]);
        }
        #pragma unroll
        for (int i = 0; i < 8; i++)
            #pragma unroll
            for (int j = 0; j < 4; j++) {
                float y = tmp[i][j] - cmp[i][j];
                float s = acc[i][j] + y;
                cmp[i][j] = (s - acc[i][j]) - y;
                acc[i][j] = s;
            }
        if (it + 1 < nt) {
            int nx = (it + 1) & 1;
            As[nx][lc+0][lr]    = a0.x; As[nx][lc+1][lr]    = a0.y; As[nx][lc+2][lr]    = a0.z; As[nx][lc+3][lr]    = a0.w;
            As[nx][lc+0][lr+64] = a1.x; As[nx][lc+1][lr+64] = a1.y; As[nx][lc+2][lr+64] = a1.z; As[nx][lc+3][lr+64] = a1.w;
            Ws[nx][lc+0][lr]    = w0.x; Ws[nx][lc+1][lr]    = w0.y; Ws[nx][lc+2][lr]    = w0.z; Ws[nx][lc+3][lr]    = w0.w;
            __syncthreads();
        }
    }
    #pragma unroll
    for (int i = 0; i < 8; i++) {
        int m = m0 + tm*8 + i;
        int n = n0 + tn*4;
        size_t di = hm_dest(m, n);
        #pragma unroll
        for (int j = 0; j < 4; j++) {
            float v = acc[i][j] + bias[n+j];
            __nv_bfloat16 h = __float2bfloat16(v);
            float r1 = v - __bfloat162float(h);
            __nv_bfloat16 md = __float2bfloat16(r1);
            float r2 = r1 - __bfloat162float(md);
            Phi[di+j]  = h;
            Pmid[di+j] = md;
            Plo[di+j]  = __float2bfloat16(r2);
        }
    }
}

// ---------------------------------------------------------------------------
// Select kernel (round-8 passing logic); emits context as bf16 hi/lo planes.
// ---------------------------------------------------------------------------
__global__ __launch_bounds__(256) void select_kernel(
    const float* __restrict__ S, const float* __restrict__ V,
    __nv_bfloat16* __restrict__ Chi, __nv_bfloat16* __restrict__ Clo)
{
    int t    = threadIdx.x;
    int qq   = t >> 5;
    int lane = t & 31;
    int bh   = blockIdx.y;
    int b    = bh >> 4, h = bh & 15;
    int q    = blockIdx.x * QB + qq;

    const float4* Srow = (const float4*)(S + ((size_t)bh*SEQ + q)*SEQ);

    unsigned u[64];
    unsigned umax = 0u;
    unsigned c0=0,c1=0,c2=0,c3=0,c4=0,c5=0;
    #pragma unroll
    for (int i = 0; i < 16; i++) {
        float4 v = Srow[i*32 + lane];
        unsigned uu[4] = { f2u(v.x), f2u(v.y), f2u(v.z), f2u(v.w) };
        #pragma unroll
        for (int s = 0; s < 4; s++) {
            unsigned w = uu[s];
            u[4*i+s] = w;
            if (w > c5) {
                c5 = w;
                if (c5 > c4) { unsigned x=c4; c4=c5; c5=x; }
                if (c4 > c3) { unsigned x=c3; c3=c4; c4=x; }
                if (c3 > c2) { unsigned x=c2; c2=c3; c3=x; }
                if (c2 > c1) { unsigned x=c1; c1=c2; c2=x; }
                if (c1 > c0) { unsigned x=c0; c0=c1; c1=x; }
            }
        }
    }
    umax = c0;
    #pragma unroll
    for (int o = 16; o; o >>= 1)
        umax = max(umax, __shfl_xor_sync(0xffffffffu, umax, o));

    unsigned lo = 0u, hi = umax;
    while (lo < hi) {
        unsigned d   = hi - lo;
        unsigned mid = lo + (d >> 1) + (d & 1u);
        int c = (c0>=mid) + (c1>=mid) + (c2>=mid) + (c3>=mid) + (c4>=mid) + (c5>=mid);
        #pragma unroll
        for (int o = 16; o; o >>= 1) c += __shfl_xor_sync(0xffffffffu, c, o);
        if (c >= UTOP) lo = mid; else hi = mid - 1;
    }
    unsigned uth = lo;
    {
        int pack = 0;
        #pragma unroll
        for (int j = 0; j < 64; j++) {
            pack += (u[j] >= uth) ? 1 : 0;
            pack += (u[j] >  uth) ? (1 << 16) : 0;
        }
        #pragma unroll
        for (int o = 16; o; o >>= 1) pack += __shfl_xor_sync(0xffffffffu, pack, o);
        int cge = pack & 0xFFFF, cgt = pack >> 16;
        if (!(cge >= UTOP && cgt < UTOP)) {
            lo = 0u; hi = umax;
            while (lo < hi) {
                unsigned d   = hi - lo;
                unsigned mid = lo + (d >> 1) + (d & 1u);
                int c = 0;
                #pragma unroll
                for (int j = 0; j < 64; j++) c += (u[j] >= mid) ? 1 : 0;
                #pragma unroll
                for (int o = 16; o; o >>= 1) c += __shfl_xor_sync(0xffffffffu, c, o);
                if (c >= UTOP) lo = mid; else hi = mid - 1;
            }
            uth = lo;
        }
    }
    const float mymax = u2f(umax);

    const float* Vb = V + ((size_t)bh*SEQ)*HD;
    float sum = 0.f, acc0 = 0.f, acc1 = 0.f;
    #pragma unroll
    for (int j = 0; j < 64; j++) {
        bool keep = (u[j] >= uth);
        float p = keep ? __expf(u2f(u[j]) - mymax) : 0.f;
        sum += p;
        unsigned msk = __ballot_sync(0xffffffffu, keep);
        int kb = ((j >> 2) << 7) + (j & 3);
        while (msk) {
            int src = __ffs(msk) - 1; msk &= msk - 1;
            float pb = __shfl_sync(0xffffffffu, p, src);
            const float* vr = Vb + (size_t)(kb + (src << 2))*HD;
            acc0 = fmaf(pb, vr[lane],      acc0);
            acc1 = fmaf(pb, vr[lane + 32], acc1);
        }
    }
    #pragma unroll
    for (int o = 16; o; o >>= 1) sum += __shfl_xor_sync(0xffffffffu, sum, o);
    float inv = 1.f / sum;

    size_t o0 = ((size_t)(b*SEQ + q))*DM + h*HD;
    float v0 = acc0 * inv, v1 = acc1 * inv;
    __nv_bfloat16 h0 = __float2bfloat16(v0);
    __nv_bfloat16 h1 = __float2bfloat16(v1);
    Chi[o0 + lane]      = h0;
    Clo[o0 + lane]      = __float2bfloat16(v0 - __bfloat162float(h0));
    Chi[o0 + lane + 32] = h1;
    Clo[o0 + lane + 32] = __float2bfloat16(v1 - __bfloat162float(h1));
}

// ---------------------------------------------------------------------------
extern "C" void kernel_launch(void* const* d_in, const int* in_sizes, int n_in,
                              void* d_out, int out_size)
{
    const float* x  = (const float*)d_in[0];
    const float* Wq = (const float*)d_in[1];
    const float* bq = (const float*)d_in[2];
    const float* Wk = (const float*)d_in[3];
    const float* bk = (const float*)d_in[4];
    const float* Wv = (const float*)d_in[5];
    const float* bv = (const float*)d_in[6];
    const float* Wo = (const float*)d_in[7];
    const float* bo = (const float*)d_in[8];
    float* out = (float*)d_out;

    float *Sp, *Vp;
    __nv_bfloat16 *xh,*xl,*Wvh,*Wvl,*Woh,*Wol,*Qh,*Qm,*Ql,*Kh,*Km,*Kl,*Ch,*Cl;
    cudaGetSymbolAddress((void**)&Sp,  g_S);
    cudaGetSymbolAddress((void**)&Vp,  g_V);
    cudaGetSymbolAddress((void**)&xh,  g_xh);  cudaGetSymbolAddress((void**)&xl,  g_xl);
    cudaGetSymbolAddress((void**)&Wvh, g_Wvh); cudaGetSymbolAddress((void**)&Wvl, g_Wvl);
    cudaGetSymbolAddress((void**)&Woh, g_Woh); cudaGetSymbolAddress((void**)&Wol, g_Wol);
    cudaGetSymbolAddress((void**)&Qh,  g_Qh);  cudaGetSymbolAddress((void**)&Qm,  g_Qm);
    cudaGetSymbolAddress((void**)&Ql,  g_Ql);
    cudaGetSymbolAddress((void**)&Kh,  g_Kh);  cudaGetSymbolAddress((void**)&Km,  g_Km);
    cudaGetSymbolAddress((void**)&Kl,  g_Kl);
    cudaGetSymbolAddress((void**)&Ch,  g_Ch);  cudaGetSymbolAddress((void**)&Cl,  g_Cl);

    const int SM2 = 2*(APU + BPU)*4;   // 50688 B
    const int SM3 = 3*(APU + BPU)*4;   // 76032 B
    cudaFuncSetAttribute(gemm_mma<2>, cudaFuncAttributeMaxDynamicSharedMemorySize, SM2);
    cudaFuncSetAttribute(gemm_mma<3>, cudaFuncAttributeMaxDynamicSharedMemorySize, SM3);

    const int M = BATCH * SEQ;   // 4096

    // input splits
    split2_kernel<<<NELM/256, 256>>>(x, xh, xl, NELM);
    split2_kernel<<<DM*DM/256, 256>>>(Wv, Wvh, Wvl, DM*DM);
    split2_kernel<<<DM*DM/256, 256>>>(Wo, Woh, Wol, DM*DM);

    // Q, K projections (Kahan FFMA, head-major bf16x3 planes out)
    gemm_2lvl<<<dim3(DM/64, M/128), 256>>>(x, DM, Wq, DM, bq, Qh, Qm, Ql, DM);
    gemm_2lvl<<<dim3(DM/64, M/128), 256>>>(x, DM, Wk, DM, bk, Kh, Km, Kl, DM);

    // V projection (mma.sync, bf16x2, head-major fp32 out)
    gemm_mma<2><<<dim3(DM/64, M/128, 1), 256, SM2>>>(
        xh, xl, (const __nv_bfloat16*)0, DM, 0,
        Wvh, Wvl, (const __nv_bfloat16*)0, DM, 0,
        bv, Vp, 0, 0, DM, 1.f, 1);

    // Scores (mma.sync, bf16x3): S[bh] = 0.125 * Q[bh] @ K[bh]^T
    gemm_mma<3><<<dim3(SEQ/64, SEQ/128, BATCH*NH), 256, SM3>>>(
        Qh, Qm, Ql, HD, (size_t)SEQ*HD,
        Kh, Km, Kl, HD, (size_t)SEQ*HD,
        (const float*)0, Sp, SEQ, (size_t)SEQ*SEQ, HD, 0.125f, 0);

    // Top-38 select + softmax + sparse AV (context emitted as bf16 hi/lo)
    select_kernel<<<dim3(SEQ/QB, BATCH*NH), 256>>>(Sp, Vp, Ch, Cl);

    // Output projection (mma.sync, bf16x2)
    gemm_mma<2><<<dim3(DM/64, M/128, 1), 256, SM2>>>(
        Ch, Cl, (const __nv_bfloat16*)0, DM, 0,
        Woh, Wol, (const __nv_bfloat16*)0, DM, 0,
        bo, out, DM, 0, DM, 1.f, 0);
}

// round 11
// speedup vs baseline: 1.3018x; 1.3018x over previous
#include <cuda_runtime.h>
#include <cuda_bf16.h>
#include <math.h>
#include <stdint.h>

#define BATCH 2
#define SEQ   2048
#define DM    1024
#define NH    16
#define HD    64
#define UTOP  38
#define QB    8
#define NELM  (BATCH*SEQ*DM)   // 4194304

// ---------------------------------------------------------------------------
// Scratch (allocation-free rule: __device__ globals)
// ---------------------------------------------------------------------------
__device__ float g_S[(size_t)BATCH*NH*SEQ*SEQ];   // 536 MB score matrix
__device__ float g_V[BATCH*NH*SEQ*HD];            // V, head-major fp32
__device__ __nv_bfloat16 g_xh[NELM],  g_xl[NELM];
__device__ __nv_bfloat16 g_Wvh[DM*DM], g_Wvl[DM*DM];
__device__ __nv_bfloat16 g_Woh[DM*DM], g_Wol[DM*DM];
__device__ __nv_bfloat16 g_Qh[NELM], g_Qm[NELM], g_Ql[NELM];   // head-major
__device__ __nv_bfloat16 g_Kh[NELM], g_Km[NELM], g_Kl[NELM];   // head-major
__device__ __nv_bfloat16 g_Ch[NELM], g_Cl[NELM];               // context hi/lo

// ---------------------------------------------------------------------------
// helpers
// ---------------------------------------------------------------------------
__device__ __forceinline__ unsigned f2u(float f) {
    unsigned u = __float_as_uint(f);
    return (u & 0x80000000u) ? ~u : (u | 0x80000000u);
}
__device__ __forceinline__ float u2f(unsigned m) {
    return __uint_as_float((m & 0x80000000u) ? (m & 0x7FFFFFFFu) : ~m);
}
__device__ __forceinline__ size_t hm_dest(int m, int n) {
    int b = m >> 11, q = m & (SEQ-1);
    int h = n >> 6,  d = n & (HD-1);
    return ((size_t)b << 21) + ((size_t)h << 17) + ((size_t)q << 6) + d;
}
__device__ __forceinline__ uint32_t smem_to_u32(const void* p) {
    uint32_t a;
    asm("{ .reg .u64 tmp; cvta.to.shared.u64 tmp, %1; cvt.u32.u64 %0, tmp; }"
        : "=r"(a) : "l"(p));
    return a;
}

// m16n8k16 bf16 MMA, fp32 accumulate (arch-neutral PTX -> HMMA)
__device__ __forceinline__ void mma16816(float c[4], const uint32_t a[4],
                                         const uint32_t b[2]) {
    asm volatile(
        "mma.sync.aligned.m16n8k16.row.col.f32.bf16.bf16.f32 "
        "{%0,%1,%2,%3}, {%4,%5,%6,%7}, {%8,%9}, {%0,%1,%2,%3};"
        : "+f"(c[0]), "+f"(c[1]), "+f"(c[2]), "+f"(c[3])
        : "r"(a[0]), "r"(a[1]), "r"(a[2]), "r"(a[3]), "r"(b[0]), "r"(b[1]));
}
// ldmatrix x4 (arch-neutral, sm_75+)
__device__ __forceinline__ void ldm_x4(uint32_t r[4], uint32_t addr) {
    asm volatile("ldmatrix.sync.aligned.m8n8.x4.shared.b16 {%0,%1,%2,%3}, [%4];"
        : "=r"(r[0]), "=r"(r[1]), "=r"(r[2]), "=r"(r[3]) : "r"(addr));
}

// ---------------------------------------------------------------------------
// bf16 split kernel
// ---------------------------------------------------------------------------
__global__ void split2_kernel(const float* __restrict__ in,
                              __nv_bfloat16* __restrict__ hi,
                              __nv_bfloat16* __restrict__ lo, int n)
{
    int i = blockIdx.x * blockDim.x + threadIdx.x;
    if (i < n) {
        float v = in[i];
        __nv_bfloat16 h = __float2bfloat16(v);
        hi[i] = h;
        lo[i] = __float2bfloat16(v - __bfloat162float(h));
    }
}

// ---------------------------------------------------------------------------
// Tensor GEMM via mma.sync + ldmatrix. C[M,N] = alpha*sum_pairs(Ai@Bj^T)+bias
// A planes [Mtot,K] bf16 row-major; B planes [Ntot,K] row-major (= col-major
// operand). Block tile 128x128, 8 warps (4m x 2n), warp tile 32x64
// (2 m16 x 8 n8), K chunks of 64 bf16. smem pitch 36 u32 (144B) ->
// ldmatrix rows hit distinct 16B banks (conflict-free).
// NSPLIT=2: pairs hh,hl,lh ; NSPLIT=3: hh,hm,mh,mm,hl,lh
// ---------------------------------------------------------------------------
#define PITCH 36
#define PLANE (128*PITCH)   // u32 per plane

template<int NSPLIT>
__global__ __launch_bounds__(256) void gemm_mma(
    const __nv_bfloat16* __restrict__ A0, const __nv_bfloat16* __restrict__ A1,
    const __nv_bfloat16* __restrict__ A2, int lda, size_t sA,
    const __nv_bfloat16* __restrict__ B0, const __nv_bfloat16* __restrict__ B1,
    const __nv_bfloat16* __restrict__ B2, int ldb, size_t sB,
    const float* __restrict__ bias,
    float* __restrict__ Cout, int ldc, size_t sC,
    int Kdim, float alpha, int headmajor)
{
    extern __shared__ uint32_t sm[];
    uint32_t* Asm = sm;                    // [NSPLIT][PLANE]
    uint32_t* Bsm = sm + NSPLIT*PLANE;     // [NSPLIT][PLANE]
    const uint32_t sbase = smem_to_u32(sm);

    const int t    = threadIdx.x;
    const int wid  = t >> 5, lane = t & 31;
    const int wm   = wid & 3, wn = wid >> 2;
    const int g    = lane >> 2;
    const int tq   = lane & 3;
    const int m0   = blockIdx.y * 128;
    const int n0   = blockIdx.x * 128;

    const uint32_t* Ap[3] = { (const uint32_t*)(A0 + blockIdx.z*sA),
                              (const uint32_t*)(A1 ? A1 + blockIdx.z*sA : A0),
                              (const uint32_t*)(A2 ? A2 + blockIdx.z*sA : A0) };
    const uint32_t* Bp[3] = { (const uint32_t*)(B0 + blockIdx.z*sB),
                              (const uint32_t*)(B1 ? B1 + blockIdx.z*sB : B0),
                              (const uint32_t*)(B2 ? B2 + blockIdx.z*sB : B0) };
    Cout += blockIdx.z * sC;

    float c[2][8][4];
    #pragma unroll
    for (int i = 0; i < 2; i++)
        #pragma unroll
        for (int j = 0; j < 8; j++)
            #pragma unroll
            for (int k = 0; k < 4; k++) c[i][j][k] = 0.f;

    const int lda2 = lda >> 1, ldb2 = ldb >> 1;
    const int nchunk = Kdim >> 6;
    const int npairs = (NSPLIT == 2) ? 3 : 6;
    const int pa[6] = {0,0,1,1,0,2};
    const int pb[6] = {0,1,0,1,2,0};

    // precomputed ldmatrix lane-address components
    const int a_row_in = (lane & 15);
    const int a_cadd   = (lane >> 4) << 2;            // 0 or 4 (u32)
    const int b_row_in = (lane & 7) + ((lane >> 4) << 3);
    const int b_cadd   = ((lane >> 3) & 1) << 2;      // 0 or 4 (u32)

    for (int cc = 0; cc < nchunk; cc++) {
        if (cc) __syncthreads();
        int kb = cc << 5;
        #pragma unroll
        for (int p = 0; p < NSPLIT; p++) {
            const uint32_t* srcA = Ap[p];
            const uint32_t* srcB = Bp[p];
            #pragma unroll
            for (int i = 0; i < 16; i++) {
                int idx = t + (i << 8);           // 0..4095
                int r = idx >> 5, col = idx & 31;
                Asm[p*PLANE + r*PITCH + col] = srcA[(size_t)(m0 + r)*lda2 + kb + col];
                Bsm[p*PLANE + r*PITCH + col] = srcB[(size_t)(n0 + r)*ldb2 + kb + col];
            }
        }
        __syncthreads();

        #pragma unroll
        for (int ks = 0; ks < 4; ks++) {
            #pragma unroll 6
            for (int pp = 0; pp < npairs; pp++) {
                uint32_t abase = sbase + 4*(pa[pp]*PLANE);
                uint32_t bbase = sbase + 4*((NSPLIT + pb[pp])*PLANE);
                uint32_t af[2][4];
                #pragma unroll
                for (int mt = 0; mt < 2; mt++) {
                    int row = wm*32 + mt*16 + a_row_in;
                    ldm_x4(af[mt], abase + 4*(row*PITCH + ks*8 + a_cadd));
                }
                uint32_t bf[8][2];
                #pragma unroll
                for (int nt2 = 0; nt2 < 4; nt2++) {
                    int row = wn*64 + nt2*16 + b_row_in;
                    uint32_t r4[4];
                    ldm_x4(r4, bbase + 4*(row*PITCH + ks*8 + b_cadd));
                    bf[nt2*2+0][0] = r4[0]; bf[nt2*2+0][1] = r4[1];
                    bf[nt2*2+1][0] = r4[2]; bf[nt2*2+1][1] = r4[3];
                }
                #pragma unroll
                for (int mt = 0; mt < 2; mt++)
                    #pragma unroll
                    for (int nt = 0; nt < 8; nt++)
                        mma16816(c[mt][nt], af[mt], bf[nt]);
            }
        }
    }

    // epilogue
    #pragma unroll
    for (int mt = 0; mt < 2; mt++) {
        #pragma unroll
        for (int half = 0; half < 2; half++) {
            int m = m0 + wm*32 + mt*16 + g + half*8;
            #pragma unroll
            for (int nt = 0; nt < 8; nt++) {
                int n = n0 + wn*64 + nt*8 + tq*2;
                float2 r;
                r.x = alpha*c[mt][nt][half*2+0] + (bias ? bias[n]   : 0.f);
                r.y = alpha*c[mt][nt][half*2+1] + (bias ? bias[n+1] : 0.f);
                float* dst = headmajor ? (Cout + hm_dest(m, n))
                                       : (Cout + (size_t)m*ldc + n);
                *(float2*)dst = r;
            }
        }
    }
}

// ---------------------------------------------------------------------------
// High-accuracy two-level (Kahan) GEMM — Q/K projections; emits 3 bf16 planes
// head-major. (Numerically identical to rounds 6-10.)
// ---------------------------------------------------------------------------
__global__ __launch_bounds__(256) void gemm_2lvl(
    const float* __restrict__ A, int lda,
    const float* __restrict__ W, int ldw,
    const float* __restrict__ bias,
    __nv_bfloat16* __restrict__ Phi, __nv_bfloat16* __restrict__ Pmid,
    __nv_bfloat16* __restrict__ Plo, int Kdim)
{
    __shared__ float As[2][16][128];
    __shared__ float Ws[2][16][64];
    int t  = threadIdx.x;
    int m0 = blockIdx.y * 128;
    int n0 = blockIdx.x * 64;
    int tm = t >> 4, tn = t & 15;
    int lr = t >> 2;
    int lc = (t & 3) << 2;

    float acc[8][4], cmp[8][4];
    #pragma unroll
    for (int i = 0; i < 8; i++)
        #pragma unroll
        for (int j = 0; j < 4; j++) { acc[i][j] = 0.f; cmp[i][j] = 0.f; }

    float4 a0, a1, w0;
    a0 = *(const float4*)(A + (size_t)(m0+lr   )*lda + lc);
    a1 = *(const float4*)(A + (size_t)(m0+lr+64)*lda + lc);
    w0 = *(const float4*)(W + (size_t)(n0+lr   )*ldw + lc);
    As[0][lc+0][lr]    = a0.x; As[0][lc+1][lr]    = a0.y; As[0][lc+2][lr]    = a0.z; As[0][lc+3][lr]    = a0.w;
    As[0][lc+0][lr+64] = a1.x; As[0][lc+1][lr+64] = a1.y; As[0][lc+2][lr+64] = a1.z; As[0][lc+3][lr+64] = a1.w;
    Ws[0][lc+0][lr]    = w0.x; Ws[0][lc+1][lr]    = w0.y; Ws[0][lc+2][lr]    = w0.z; Ws[0][lc+3][lr]    = w0.w;
    __syncthreads();

    int nt = Kdim >> 4;
    for (int it = 0; it < nt; it++) {
        int cur = it & 1;
        if (it + 1 < nt) {
            int k0 = (it + 1) << 4;
            a0 = *(const float4*)(A + (size_t)(m0+lr   )*lda + k0 + lc);
            a1 = *(const float4*)(A + (size_t)(m0+lr+64)*lda + k0 + lc);
            w0 = *(const float4*)(W + (size_t)(n0+lr   )*ldw + k0 + lc);
        }
        float tmp[8][4];
        #pragma unroll
        for (int i = 0; i < 8; i++)
            #pragma unroll
            for (int j = 0; j < 4; j++) tmp[i][j] = 0.f;
        #pragma unroll
        for (int kk = 0; kk < 16; kk++) {
            float a[8], bb[4];
            *(float4*)(a)    = *(const float4*)&As[cur][kk][tm*8];
            *(float4*)(a+4)  = *(const float4*)&As[cur][kk][tm*8+4];
            *(float4*)(bb)   = *(const float4*)&Ws[cur][kk][tn*4];
            #pragma unroll
            for (int i = 0; i < 8; i++)
                #pragma unroll
                for (int j = 0; j < 4; j++)
                    tmp[i][j] = fmaf(a[i], bb[j], tmp[i][j]);
        }
        #pragma unroll
        for (int i = 0; i < 8; i++)
            #pragma unroll
            for (int j = 0; j < 4; j++) {
                float y = tmp[i][j] - cmp[i][j];
                float s = acc[i][j] + y;
                cmp[i][j] = (s - acc[i][j]) - y;
                acc[i][j] = s;
            }
        if (it + 1 < nt) {
            int nx = (it + 1) & 1;
            As[nx][lc+0][lr]    = a0.x; As[nx][lc+1][lr]    = a0.y; As[nx][lc+2][lr]    = a0.z; As[nx][lc+3][lr]    = a0.w;
            As[nx][lc+0][lr+64] = a1.x; As[nx][lc+1][lr+64] = a1.y; As[nx][lc+2][lr+64] = a1.z; As[nx][lc+3][lr+64] = a1.w;
            Ws[nx][lc+0][lr]    = w0.x; Ws[nx][lc+1][lr]    = w0.y; Ws[nx][lc+2][lr]    = w0.z; Ws[nx][lc+3][lr]    = w0.w;
            __syncthreads();
        }
    }
    #pragma unroll
    for (int i = 0; i < 8; i++) {
        int m = m0 + tm*8 + i;
        int n = n0 + tn*4;
        size_t di = hm_dest(m, n);
        #pragma unroll
        for (int j = 0; j < 4; j++) {
            float v = acc[i][j] + bias[n+j];
            __nv_bfloat16 h = __float2bfloat16(v);
            float r1 = v - __bfloat162float(h);
            __nv_bfloat16 md = __float2bfloat16(r1);
            float r2 = r1 - __bfloat162float(md);
            Phi[di+j]  = h;
            Pmid[di+j] = md;
            Plo[di+j]  = __float2bfloat16(r2);
        }
    }
}

// ---------------------------------------------------------------------------
// Select kernel (round-8/10 passing logic); emits context as bf16 hi/lo.
// ---------------------------------------------------------------------------
__global__ __launch_bounds__(256) void select_kernel(
    const float* __restrict__ S, const float* __restrict__ V,
    __nv_bfloat16* __restrict__ Chi, __nv_bfloat16* __restrict__ Clo)
{
    int t    = threadIdx.x;
    int qq   = t >> 5;
    int lane = t & 31;
    int bh   = blockIdx.y;
    int b    = bh >> 4, h = bh & 15;
    int q    = blockIdx.x * QB + qq;

    const float4* Srow = (const float4*)(S + ((size_t)bh*SEQ + q)*SEQ);

    unsigned u[64];
    unsigned umax = 0u;
    unsigned c0=0,c1=0,c2=0,c3=0,c4=0,c5=0;
    #pragma unroll
    for (int i = 0; i < 16; i++) {
        float4 v = Srow[i*32 + lane];
        unsigned uu[4] = { f2u(v.x), f2u(v.y), f2u(v.z), f2u(v.w) };
        #pragma unroll
        for (int s = 0; s < 4; s++) {
            unsigned w = uu[s];
            u[4*i+s] = w;
            if (w > c5) {
                c5 = w;
                if (c5 > c4) { unsigned x=c4; c4=c5; c5=x; }
                if (c4 > c3) { unsigned x=c3; c3=c4; c4=x; }
                if (c3 > c2) { unsigned x=c2; c2=c3; c3=x; }
                if (c2 > c1) { unsigned x=c1; c1=c2; c2=x; }
                if (c1 > c0) { unsigned x=c0; c0=c1; c1=x; }
            }
        }
    }
    umax = c0;
    #pragma unroll
    for (int o = 16; o; o >>= 1)
        umax = max(umax, __shfl_xor_sync(0xffffffffu, umax, o));

    unsigned lo = 0u, hi = umax;
    while (lo < hi) {
        unsigned d   = hi - lo;
        unsigned mid = lo + (d >> 1) + (d & 1u);
        int c = (c0>=mid) + (c1>=mid) + (c2>=mid) + (c3>=mid) + (c4>=mid) + (c5>=mid);
        #pragma unroll
        for (int o = 16; o; o >>= 1) c += __shfl_xor_sync(0xffffffffu, c, o);
        if (c >= UTOP) lo = mid; else hi = mid - 1;
    }
    unsigned uth = lo;
    {
        int pack = 0;
        #pragma unroll
        for (int j = 0; j < 64; j++) {
            pack += (u[j] >= uth) ? 1 : 0;
            pack += (u[j] >  uth) ? (1 << 16) : 0;
        }
        #pragma unroll
        for (int o = 16; o; o >>= 1) pack += __shfl_xor_sync(0xffffffffu, pack, o);
        int cge = pack & 0xFFFF, cgt = pack >> 16;
        if (!(cge >= UTOP && cgt < UTOP)) {
            lo = 0u; hi = umax;
            while (lo < hi) {
                unsigned d   = hi - lo;
                unsigned mid = lo + (d >> 1) + (d & 1u);
                int c = 0;
                #pragma unroll
                for (int j = 0; j < 64; j++) c += (u[j] >= mid) ? 1 : 0;
                #pragma unroll
                for (int o = 16; o; o >>= 1) c += __shfl_xor_sync(0xffffffffu, c, o);
                if (c >= UTOP) lo = mid; else hi = mid - 1;
            }
            uth = lo;
        }
    }
    const float mymax = u2f(umax);

    const float* Vb = V + ((size_t)bh*SEQ)*HD;
    float sum = 0.f, acc0 = 0.f, acc1 = 0.f;
    #pragma unroll
    for (int j = 0; j < 64; j++) {
        bool keep = (u[j] >= uth);
        float p = keep ? __expf(u2f(u[j]) - mymax) : 0.f;
        sum += p;
        unsigned msk = __ballot_sync(0xffffffffu, keep);
        int kb = ((j >> 2) << 7) + (j & 3);
        while (msk) {
            int src = __ffs(msk) - 1; msk &= msk - 1;
            float pb = __shfl_sync(0xffffffffu, p, src);
            const float* vr = Vb + (size_t)(kb + (src << 2))*HD;
            acc0 = fmaf(pb, vr[lane],      acc0);
            acc1 = fmaf(pb, vr[lane + 32], acc1);
        }
    }
    #pragma unroll
    for (int o = 16; o; o >>= 1) sum += __shfl_xor_sync(0xffffffffu, sum, o);
    float inv = 1.f / sum;

    size_t o0 = ((size_t)(b*SEQ + q))*DM + h*HD;
    float v0 = acc0 * inv, v1 = acc1 * inv;
    __nv_bfloat16 h0 = __float2bfloat16(v0);
    __nv_bfloat16 h1 = __float2bfloat16(v1);
    Chi[o0 + lane]      = h0;
    Clo[o0 + lane]      = __float2bfloat16(v0 - __bfloat162float(h0));
    Chi[o0 + lane + 32] = h1;
    Clo[o0 + lane + 32] = __float2bfloat16(v1 - __bfloat162float(h1));
}

// ---------------------------------------------------------------------------
extern "C" void kernel_launch(void* const* d_in, const int* in_sizes, int n_in,
                              void* d_out, int out_size)
{
    const float* x  = (const float*)d_in[0];
    const float* Wq = (const float*)d_in[1];
    const float* bq = (const float*)d_in[2];
    const float* Wk = (const float*)d_in[3];
    const float* bk = (const float*)d_in[4];
    const float* Wv = (const float*)d_in[5];
    const float* bv = (const float*)d_in[6];
    const float* Wo = (const float*)d_in[7];
    const float* bo = (const float*)d_in[8];
    float* out = (float*)d_out;

    float *Sp, *Vp;
    __nv_bfloat16 *xh,*xl,*Wvh,*Wvl,*Woh,*Wol,*Qh,*Qm,*Ql,*Kh,*Km,*Kl,*Ch,*Cl;
    cudaGetSymbolAddress((void**)&Sp,  g_S);
    cudaGetSymbolAddress((void**)&Vp,  g_V);
    cudaGetSymbolAddress((void**)&xh,  g_xh);  cudaGetSymbolAddress((void**)&xl,  g_xl);
    cudaGetSymbolAddress((void**)&Wvh, g_Wvh); cudaGetSymbolAddress((void**)&Wvl, g_Wvl);
    cudaGetSymbolAddress((void**)&Woh, g_Woh); cudaGetSymbolAddress((void**)&Wol, g_Wol);
    cudaGetSymbolAddress((void**)&Qh,  g_Qh);  cudaGetSymbolAddress((void**)&Qm,  g_Qm);
    cudaGetSymbolAddress((void**)&Ql,  g_Ql);
    cudaGetSymbolAddress((void**)&Kh,  g_Kh);  cudaGetSymbolAddress((void**)&Km,  g_Km);
    cudaGetSymbolAddress((void**)&Kl,  g_Kl);
    cudaGetSymbolAddress((void**)&Ch,  g_Ch);  cudaGetSymbolAddress((void**)&Cl,  g_Cl);

    const int SM2 = 2*2*PLANE*4;   // 73728 B
    const int SM3 = 3*2*PLANE*4;   // 110592 B
    cudaFuncSetAttribute(gemm_mma<2>, cudaFuncAttributeMaxDynamicSharedMemorySize, SM2);
    cudaFuncSetAttribute(gemm_mma<3>, cudaFuncAttributeMaxDynamicSharedMemorySize, SM3);

    const int M = BATCH * SEQ;   // 4096

    // input splits
    split2_kernel<<<NELM/256, 256>>>(x, xh, xl, NELM);
    split2_kernel<<<DM*DM/256, 256>>>(Wv, Wvh, Wvl, DM*DM);
    split2_kernel<<<DM*DM/256, 256>>>(Wo, Woh, Wol, DM*DM);

    // Q, K projections (Kahan FFMA, head-major bf16x3 planes out)
    gemm_2lvl<<<dim3(DM/64, M/128), 256>>>(x, DM, Wq, DM, bq, Qh, Qm, Ql, DM);
    gemm_2lvl<<<dim3(DM/64, M/128), 256>>>(x, DM, Wk, DM, bk, Kh, Km, Kl, DM);

    // V projection (mma+ldmatrix, bf16x2, head-major fp32 out)
    gemm_mma<2><<<dim3(DM/128, M/128, 1), 256, SM2>>>(
        xh, xl, (const __nv_bfloat16*)0, DM, 0,
        Wvh, Wvl, (const __nv_bfloat16*)0, DM, 0,
        bv, Vp, 0, 0, DM, 1.f, 1);

    // Scores (mma+ldmatrix, bf16x3): S[bh] = 0.125 * Q[bh] @ K[bh]^T
    gemm_mma<3><<<dim3(SEQ/128, SEQ/128, BATCH*NH), 256, SM3>>>(
        Qh, Qm, Ql, HD, (size_t)SEQ*HD,
        Kh, Km, Kl, HD, (size_t)SEQ*HD,
        (const float*)0, Sp, SEQ, (size_t)SEQ*SEQ, HD, 0.125f, 0);

    // Top-38 select + softmax + sparse AV (context emitted as bf16 hi/lo)
    select_kernel<<<dim3(SEQ/QB, BATCH*NH), 256>>>(Sp, Vp, Ch, Cl);

    // Output projection (mma+ldmatrix, bf16x2)
    gemm_mma<2><<<dim3(DM/128, M/128, 1), 256, SM2>>>(
        Ch, Cl, (const __nv_bfloat16*)0, DM, 0,
        Woh, Wol, (const __nv_bfloat16*)0, DM, 0,
        bo, out, DM, 0, DM, 1.f, 0);
}